// round 1
// baseline (speedup 1.0000x reference)
#include <cuda_runtime.h>
#include <cuda_bf16.h>

// if_encoder: integrate-and-fire with soft reset.
//   inputs : d_in[0] input_spikes [B=64, D=4096, T=128] f32 (T contiguous)
//            d_in[1] states       [B, D] f32
//            d_in[2] threshold    scalar f32
//   output : d_out = spikes [B, D, T] f32  followed by  v_final [B, D] f32
//
// One thread per (b,d) row, sequential scan over T (reference FP order kept
// bit-exact). Global traffic staged through shared memory so every global
// transaction is a fully-coalesced float4 access.

static constexpr int B_ = 64;
static constexpr int D_ = 4096;
static constexpr int T_ = 128;
static constexpr long long ROWS = (long long)B_ * D_;     // 262144
static constexpr int BLOCK = 256;
static constexpr int TT = 32;                              // time-tile (floats)
static constexpr int TILES = T_ / TT;                      // 4
static constexpr int SROW = TT + 1;                        // 33: bank-conflict pad

__global__ __launch_bounds__(BLOCK)
void if_encoder_kernel(const float* __restrict__ x,
                       const float* __restrict__ states,
                       const float* __restrict__ thr_ptr,
                       float* __restrict__ spikes,
                       float* __restrict__ vfinal,
                       int write_vfinal) {
    __shared__ float s[BLOCK * SROW];   // 33792 B

    const int tid = threadIdx.x;
    const long long row0 = (long long)blockIdx.x * BLOCK;
    const long long row  = row0 + tid;

    const float thr = thr_ptr[0];
    float v = states[row];

    const float4* __restrict__ x4  = reinterpret_cast<const float4*>(x);
    float4* __restrict__       sp4 = reinterpret_cast<float4*>(spikes);
    // per row: T_/4 = 32 float4; per tile: 8 float4 per row.

    #pragma unroll
    for (int tile = 0; tile < TILES; ++tile) {
        const int c4base = tile * (TT / 4);   // float4 column base

        // ---- coalesced load: 2048 float4 per block, 8 per thread ----
        #pragma unroll
        for (int k = 0; k < 8; ++k) {
            const int e  = k * BLOCK + tid;   // 0..2047
            const int r  = e >> 3;            // row within block
            const int c4 = e & 7;             // float4 col within tile
            const float4 f = x4[(row0 + r) * (T_ / 4) + c4base + c4];
            float* d = &s[r * SROW + c4 * 4];
            d[0] = f.x; d[1] = f.y; d[2] = f.z; d[3] = f.w;
        }
        __syncthreads();

        // ---- sequential scan of this thread's row (conflict-free smem) ----
        float* my = &s[tid * SROW];
        #pragma unroll
        for (int t = 0; t < TT; ++t) {
            const float xv = my[t];
            v += xv;                                   // integrate (ref order)
            const float spike = (v >= thr) ? 1.0f : 0.0f;
            v = fmaf(-spike, thr, v);                  // soft reset, bit-exact
            my[t] = spike;                             // overwrite in place
        }
        __syncthreads();

        // ---- coalesced store of spikes ----
        #pragma unroll
        for (int k = 0; k < 8; ++k) {
            const int e  = k * BLOCK + tid;
            const int r  = e >> 3;
            const int c4 = e & 7;
            const float* d = &s[r * SROW + c4 * 4];
            float4 f;
            f.x = d[0]; f.y = d[1]; f.z = d[2]; f.w = d[3];
            sp4[(row0 + r) * (T_ / 4) + c4base + c4] = f;
        }
        __syncthreads();
    }

    if (write_vfinal) {
        vfinal[row] = v;
    }
}

extern "C" void kernel_launch(void* const* d_in, const int* in_sizes, int n_in,
                              void* d_out, int out_size) {
    const float* x      = (const float*)d_in[0];
    const float* states = (const float*)d_in[1];
    const float* thr    = (const float*)d_in[2];

    float* out    = (float*)d_out;
    float* spikes = out;
    float* vfin   = out + ROWS * T_;

    const long long need = ROWS * T_ + ROWS;
    const int write_vfinal = ((long long)out_size >= need) ? 1 : 0;

    const int grid = (int)(ROWS / BLOCK);   // 1024
    if_encoder_kernel<<<grid, BLOCK>>>(x, states, thr, spikes, vfin, write_vfinal);
}